// round 3
// baseline (speedup 1.0000x reference)
#include <cuda_runtime.h>
#include <cuda_bf16.h>

#define NN    50000
#define DIN   128
#define HH    64
#define CC    2
#define EMAX  800000

// ---------------- scratch (static __device__, no allocation) ----------------
__device__ int d_flag64;
__device__ __align__(16) int   d_cnt[NN];
__device__ __align__(16) int   d_rp [NN + 1];
__device__ __align__(16) int   d_cur[NN];
__device__ __align__(16) int   d_col[EMAX];
__device__ __align__(16) float d_dinv[NN];
__device__ __align__(16) float d_g1[(size_t)NN * HH];   // (x@W1)*dinv[src]
__device__ __align__(16) float d_g2[NN * CC];           // layer-2 pre-scatter msgs

__device__ __forceinline__ int edge_at(const void* p, long long i) {
    if (d_flag64) return (int)((const long long*)p)[i];
    return ((const int*)p)[i];
}

// ---------------- dtype detection: int64 vs int32 edge_index ----------------
__global__ void k_detect(const int* __restrict__ p) {
    __shared__ int ok;
    if (threadIdx.x == 0) ok = 1;
    __syncthreads();
    int bad = 0;
    for (int i = threadIdx.x; i < 1024; i += blockDim.x) {
        int lo = p[2 * i], hi = p[2 * i + 1];
        if (hi != 0 || lo < 0 || lo >= NN) bad = 1;
    }
    if (bad) atomicAnd(&ok, 0);
    __syncthreads();
    if (threadIdx.x == 0) d_flag64 = ok;
}

__global__ void k_zero() {
    int i = blockIdx.x * blockDim.x + threadIdx.x;
    if (i < NN) d_cnt[i] = 0;
}

// count in-degree (dst half only)
__global__ void k_count(const void* __restrict__ p, int E) {
    int i = blockIdx.x * blockDim.x + threadIdx.x;
    if (i >= E) return;
    int d = edge_at(p, (long long)E + i);
    atomicAdd(&d_cnt[d], 1);
}

// single-block scan: row_ptr (exclusive), cursor init, dinv = rsqrt(1+deg)
__global__ void k_scan() {
    __shared__ int sm[1024];
    const int tid = threadIdx.x;
    const int CH = (NN + 1023) / 1024;
    const int base = tid * CH;
    const int end  = min(base + CH, NN);
    int s = 0;
    for (int i = base; i < end; i++) s += d_cnt[i];
    sm[tid] = s;
    __syncthreads();
    for (int off = 1; off < 1024; off <<= 1) {
        int v = (tid >= off) ? sm[tid - off] : 0;
        __syncthreads();
        sm[tid] += v;
        __syncthreads();
    }
    int run = (tid > 0) ? sm[tid - 1] : 0;
    for (int i = base; i < end; i++) {
        int c = d_cnt[i];
        d_rp[i]  = run;
        d_cur[i] = run;
        d_dinv[i] = rsqrtf((float)(1 + c));
        run += c;
    }
    if (tid == 1023) d_rp[NN] = run;
}

// fill CSR col array (order nondeterministic; sum tolerance covers it)
__global__ void k_bucket(const void* __restrict__ p, int E) {
    int e = blockIdx.x * blockDim.x + threadIdx.x;
    if (e >= E) return;
    int s = edge_at(p, e);
    int d = edge_at(p, (long long)E + e);
    int pos = atomicAdd(&d_cur[d], 1);
    d_col[pos] = s;
}

// ---------------- layer 1 GEMM: g1 = (x @ W1) * dinv ------------------------
// tile 128 nodes x 64 outs, 256 threads, 8x4 micro-tile, K split in 2 halves
__global__ void __launch_bounds__(256) k_gemm1(const float* __restrict__ x,
                                               const float* __restrict__ W1) {
    __shared__ float xs[128][64];   // 32 KB
    __shared__ float Ws[64][64];    // 16 KB
    const int tid = threadIdx.x;
    const int tx = tid & 15;        // out group: o = 4*tx
    const int ty = tid >> 4;        // node group: n = ty*8 + j
    const int nb = blockIdx.x * 128;

    float acc[8][4];
    #pragma unroll
    for (int j = 0; j < 8; j++)
        #pragma unroll
        for (int c = 0; c < 4; c++) acc[j][c] = 0.0f;

    for (int kk = 0; kk < DIN; kk += 64) {
        __syncthreads();
        // stage W1 rows kk..kk+63: 1024 float4
        for (int i = tid; i < 1024; i += 256) {
            int r = i >> 4, c4 = i & 15;
            ((float4*)Ws[r])[c4] = ((const float4*)(W1 + (size_t)(kk + r) * HH))[c4];
        }
        // stage x tile: 128 rows x 64 cols = 2048 float4
        for (int i = tid; i < 2048; i += 256) {
            int r = i >> 4, c4 = i & 15;
            int node = nb + r;
            float4 v = make_float4(0.f, 0.f, 0.f, 0.f);
            if (node < NN) v = ((const float4*)(x + (size_t)node * DIN + kk))[c4];
            ((float4*)xs[r])[c4] = v;
        }
        __syncthreads();

        #pragma unroll 8
        for (int k = 0; k < 64; k++) {
            float4 w = ((float4*)Ws[k])[tx];
            #pragma unroll
            for (int j = 0; j < 8; j++) {
                float xv = xs[ty * 8 + j][k];
                acc[j][0] = fmaf(xv, w.x, acc[j][0]);
                acc[j][1] = fmaf(xv, w.y, acc[j][1]);
                acc[j][2] = fmaf(xv, w.z, acc[j][2]);
                acc[j][3] = fmaf(xv, w.w, acc[j][3]);
            }
        }
    }

    #pragma unroll
    for (int j = 0; j < 8; j++) {
        int node = nb + ty * 8 + j;
        if (node < NN) {
            float di = d_dinv[node];
            float4 v = make_float4(acc[j][0] * di, acc[j][1] * di,
                                   acc[j][2] * di, acc[j][3] * di);
            ((float4*)(d_g1 + (size_t)node * HH))[tx] = v;
        }
    }
}

// ------- fused: aggregate layer1 (gather) + relu/bias + GEMM2 + scale -------
// warp per node: lane holds cols [2*lane, 2*lane+1]
__global__ void __launch_bounds__(256) k_agg1(const float* __restrict__ b1,
                                              const float* __restrict__ W2) {
    __shared__ float w2s[HH * CC];
    __shared__ float b1s[HH];
    const int tid = threadIdx.x;
    if (tid < HH * CC) w2s[tid] = W2[tid];
    if (tid < HH)      b1s[tid] = b1[tid];
    __syncthreads();

    const int warp = tid >> 5, lane = tid & 31;
    const int node = blockIdx.x * 8 + warp;
    if (node >= NN) return;

    const float2* __restrict__ g1v = (const float2*)d_g1;
    float2 acc = g1v[(size_t)node * 32 + lane];   // self-loop term

    const int rs = d_rp[node], re = d_rp[node + 1];
    int k = rs;
    int s = (k < re) ? d_col[k] : 0;
    while (k < re) {
        int sn = (k + 1 < re) ? d_col[k + 1] : 0;
        float2 v = g1v[(size_t)s * 32 + lane];
        acc.x += v.x; acc.y += v.y;
        s = sn; ++k;
    }

    const float di = d_dinv[node];
    float h0 = fmaxf(fmaf(di, acc.x, b1s[2 * lane    ]), 0.0f);
    float h1 = fmaxf(fmaf(di, acc.y, b1s[2 * lane + 1]), 0.0f);
    float a0 = h0 * w2s[4 * lane + 0] + h1 * w2s[4 * lane + 2];
    float a1 = h0 * w2s[4 * lane + 1] + h1 * w2s[4 * lane + 3];
    #pragma unroll
    for (int off = 16; off; off >>= 1) {
        a0 += __shfl_xor_sync(0xffffffff, a0, off);
        a1 += __shfl_xor_sync(0xffffffff, a1, off);
    }
    if (lane == 0)
        *(float2*)(d_g2 + node * CC) = make_float2(a0 * di, a1 * di);
}

// ---------- layer 2 aggregate (gather) + bias -> out, thread per node -------
__global__ void k_agg2(float* __restrict__ out, const float* __restrict__ b2) {
    int i = blockIdx.x * blockDim.x + threadIdx.x;
    if (i >= NN) return;
    const float2* __restrict__ g2v = (const float2*)d_g2;
    float2 acc = g2v[i];   // self-loop
    const int rs = d_rp[i], re = d_rp[i + 1];
    int k = rs;
    for (; k + 3 < re; k += 4) {
        int s0 = d_col[k], s1 = d_col[k + 1], s2 = d_col[k + 2], s3 = d_col[k + 3];
        float2 v0 = g2v[s0], v1 = g2v[s1], v2 = g2v[s2], v3 = g2v[s3];
        acc.x += (v0.x + v1.x) + (v2.x + v3.x);
        acc.y += (v0.y + v1.y) + (v2.y + v3.y);
    }
    for (; k < re; k++) {
        float2 v = g2v[d_col[k]];
        acc.x += v.x; acc.y += v.y;
    }
    const float di = d_dinv[i];
    *(float2*)(out + i * CC) =
        make_float2(fmaf(di, acc.x, b2[0]), fmaf(di, acc.y, b2[1]));
}

// ---------------- launch ----------------------------------------------------
extern "C" void kernel_launch(void* const* d_in, const int* in_sizes, int n_in,
                              void* d_out, int out_size) {
    const float* x  = (const float*)d_in[0];
    const void*  ei = d_in[1];
    const float* b1 = (const float*)d_in[3];
    const float* W1 = (const float*)d_in[2];
    const float* W2 = (const float*)d_in[4];
    const float* b2 = (const float*)d_in[5];
    float* out = (float*)d_out;

    const int E = in_sizes[1] / 2;

    k_detect<<<1, 256>>>((const int*)ei);
    k_zero  <<<(NN + 255) / 256, 256>>>();
    k_count <<<(E + 255) / 256, 256>>>(ei, E);
    k_scan  <<<1, 1024>>>();
    k_bucket<<<(E + 255) / 256, 256>>>(ei, E);
    k_gemm1 <<<(NN + 127) / 128, 256>>>(x, W1);
    k_agg1  <<<(NN + 7) / 8, 256>>>(b1, W2);
    k_agg2  <<<(NN + 255) / 256, 256>>>(out, b2);
}

// round 4
// speedup vs baseline: 2.3195x; 2.3195x over previous
#include <cuda_runtime.h>
#include <cuda_bf16.h>

#define NN    50000
#define DIN   128
#define HH    64
#define CC    2
#define EMAX  800000
#define NB    ((NN + 255) / 256)   // 196 scan blocks

// ---------------- scratch (static __device__, no allocation) ----------------
__device__ int d_flag64;
__device__ __align__(16) int   d_cnt[NN];
__device__ __align__(16) int   d_rp [NN + 1];
__device__ __align__(16) int   d_cur[NN];
__device__ __align__(16) int   d_bsum[NB];
__device__ __align__(16) int   d_boff[NB];
__device__ __align__(16) int   d_col[EMAX];
__device__ __align__(16) float d_dinv[NN];
__device__ __align__(16) float d_g1[(size_t)NN * HH];   // (x@W1)*dinv[src]
__device__ __align__(16) float d_g2[NN * CC];           // layer-2 pre-scatter msgs

__device__ __forceinline__ int edge_at(const void* p, long long i) {
    if (d_flag64) return (int)((const long long*)p)[i];
    return ((const int*)p)[i];
}

// ---------------- dtype detection: int64 vs int32 edge_index ----------------
__global__ void k_detect(const int* __restrict__ p) {
    __shared__ int ok;
    if (threadIdx.x == 0) ok = 1;
    __syncthreads();
    int bad = 0;
    for (int i = threadIdx.x; i < 1024; i += blockDim.x) {
        int lo = p[2 * i], hi = p[2 * i + 1];
        if (hi != 0 || lo < 0 || lo >= NN) bad = 1;
    }
    if (bad) atomicAnd(&ok, 0);
    __syncthreads();
    if (threadIdx.x == 0) d_flag64 = ok;
}

__global__ void k_zero() {
    int i = blockIdx.x * blockDim.x + threadIdx.x;
    if (i < NN) d_cnt[i] = 0;
}

// count in-degree (dst half only)
__global__ void k_count(const void* __restrict__ p, int E) {
    int i = blockIdx.x * blockDim.x + threadIdx.x;
    if (i >= E) return;
    int d = edge_at(p, (long long)E + i);
    atomicAdd(&d_cnt[d], 1);
}

// ---------------- two-level scan --------------------------------------------
// stage 1: per-block exclusive scan of d_cnt -> d_rp (block-local), block sum
__global__ void __launch_bounds__(256) k_scan1() {
    __shared__ int sm[256];
    const int tid = threadIdx.x;
    const int i   = blockIdx.x * 256 + tid;
    int v = (i < NN) ? d_cnt[i] : 0;
    sm[tid] = v;
    __syncthreads();
    #pragma unroll
    for (int off = 1; off < 256; off <<= 1) {
        int t = (tid >= off) ? sm[tid - off] : 0;
        __syncthreads();
        sm[tid] += t;
        __syncthreads();
    }
    if (i < NN) d_rp[i] = sm[tid] - v;          // exclusive, block-local
    if (tid == 255) d_bsum[blockIdx.x] = sm[255];
}

// stage 2: exclusive scan of the NB block sums (single small block)
__global__ void __launch_bounds__(256) k_scan2() {
    __shared__ int sm[256];
    const int tid = threadIdx.x;
    int v = (tid < NB) ? d_bsum[tid] : 0;
    sm[tid] = v;
    __syncthreads();
    #pragma unroll
    for (int off = 1; off < 256; off <<= 1) {
        int t = (tid >= off) ? sm[tid - off] : 0;
        __syncthreads();
        sm[tid] += t;
        __syncthreads();
    }
    if (tid < NB) d_boff[tid] = sm[tid] - v;
    if (tid == NB - 1) d_rp[NN] = sm[tid];      // total edge count
}

// stage 3: add block offsets; init cursor; dinv = rsqrt(1+deg)
__global__ void __launch_bounds__(256) k_scan3() {
    const int i = blockIdx.x * 256 + threadIdx.x;
    if (i >= NN) return;
    int r = d_rp[i] + d_boff[blockIdx.x];
    d_rp[i]  = r;
    d_cur[i] = r;
    d_dinv[i] = rsqrtf((float)(1 + d_cnt[i]));
}

// fill CSR col array (order nondeterministic; sum tolerance covers it)
__global__ void k_bucket(const void* __restrict__ p, int E) {
    int e = blockIdx.x * blockDim.x + threadIdx.x;
    if (e >= E) return;
    int s = edge_at(p, e);
    int d = edge_at(p, (long long)E + e);
    int pos = atomicAdd(&d_cur[d], 1);
    d_col[pos] = s;
}

// ---------------- layer 1 GEMM: g1 = (x @ W1) * dinv ------------------------
// tile 128 nodes x 64 outs, 256 threads, 8x4 micro-tile, K split in 2 halves
__global__ void __launch_bounds__(256) k_gemm1(const float* __restrict__ x,
                                               const float* __restrict__ W1) {
    __shared__ float xs[128][64];   // 32 KB
    __shared__ float Ws[64][64];    // 16 KB
    const int tid = threadIdx.x;
    const int tx = tid & 15;        // out group: o = 4*tx
    const int ty = tid >> 4;        // node group: n = ty*8 + j
    const int nb = blockIdx.x * 128;

    float acc[8][4];
    #pragma unroll
    for (int j = 0; j < 8; j++)
        #pragma unroll
        for (int c = 0; c < 4; c++) acc[j][c] = 0.0f;

    for (int kk = 0; kk < DIN; kk += 64) {
        __syncthreads();
        // stage W1 rows kk..kk+63: 1024 float4
        for (int i = tid; i < 1024; i += 256) {
            int r = i >> 4, c4 = i & 15;
            ((float4*)Ws[r])[c4] = ((const float4*)(W1 + (size_t)(kk + r) * HH))[c4];
        }
        // stage x tile: 128 rows x 64 cols = 2048 float4
        for (int i = tid; i < 2048; i += 256) {
            int r = i >> 4, c4 = i & 15;
            int node = nb + r;
            float4 v = make_float4(0.f, 0.f, 0.f, 0.f);
            if (node < NN) v = ((const float4*)(x + (size_t)node * DIN + kk))[c4];
            ((float4*)xs[r])[c4] = v;
        }
        __syncthreads();

        #pragma unroll 8
        for (int k = 0; k < 64; k++) {
            float4 w = ((float4*)Ws[k])[tx];
            #pragma unroll
            for (int j = 0; j < 8; j++) {
                float xv = xs[ty * 8 + j][k];
                acc[j][0] = fmaf(xv, w.x, acc[j][0]);
                acc[j][1] = fmaf(xv, w.y, acc[j][1]);
                acc[j][2] = fmaf(xv, w.z, acc[j][2]);
                acc[j][3] = fmaf(xv, w.w, acc[j][3]);
            }
        }
    }

    #pragma unroll
    for (int j = 0; j < 8; j++) {
        int node = nb + ty * 8 + j;
        if (node < NN) {
            float di = d_dinv[node];
            float4 v = make_float4(acc[j][0] * di, acc[j][1] * di,
                                   acc[j][2] * di, acc[j][3] * di);
            ((float4*)(d_g1 + (size_t)node * HH))[tx] = v;
        }
    }
}

// ------- fused: aggregate layer1 (gather) + relu/bias + GEMM2 + scale -------
// warp per node: lane holds cols [2*lane, 2*lane+1]
__global__ void __launch_bounds__(256) k_agg1(const float* __restrict__ b1,
                                              const float* __restrict__ W2) {
    __shared__ float w2s[HH * CC];
    __shared__ float b1s[HH];
    const int tid = threadIdx.x;
    if (tid < HH * CC) w2s[tid] = W2[tid];
    if (tid < HH)      b1s[tid] = b1[tid];
    __syncthreads();

    const int warp = tid >> 5, lane = tid & 31;
    const int node = blockIdx.x * 8 + warp;
    if (node >= NN) return;

    const float2* __restrict__ g1v = (const float2*)d_g1;
    float2 acc = g1v[(size_t)node * 32 + lane];   // self-loop term

    const int rs = d_rp[node], re = d_rp[node + 1];
    for (int k = rs; k < re; k++) {
        float2 v = g1v[(size_t)d_col[k] * 32 + lane];
        acc.x += v.x; acc.y += v.y;
    }

    const float di = d_dinv[node];
    float h0 = fmaxf(fmaf(di, acc.x, b1s[2 * lane    ]), 0.0f);
    float h1 = fmaxf(fmaf(di, acc.y, b1s[2 * lane + 1]), 0.0f);
    float a0 = h0 * w2s[4 * lane + 0] + h1 * w2s[4 * lane + 2];
    float a1 = h0 * w2s[4 * lane + 1] + h1 * w2s[4 * lane + 3];
    #pragma unroll
    for (int off = 16; off; off >>= 1) {
        a0 += __shfl_xor_sync(0xffffffff, a0, off);
        a1 += __shfl_xor_sync(0xffffffff, a1, off);
    }
    if (lane == 0)
        *(float2*)(d_g2 + node * CC) = make_float2(a0 * di, a1 * di);
}

// ---------- layer 2 aggregate (gather) + bias -> out, thread per node -------
__global__ void k_agg2(float* __restrict__ out, const float* __restrict__ b2) {
    int i = blockIdx.x * blockDim.x + threadIdx.x;
    if (i >= NN) return;
    const float2* __restrict__ g2v = (const float2*)d_g2;
    float2 acc = g2v[i];   // self-loop
    const int rs = d_rp[i], re = d_rp[i + 1];
    int k = rs;
    for (; k + 3 < re; k += 4) {
        int s0 = d_col[k], s1 = d_col[k + 1], s2 = d_col[k + 2], s3 = d_col[k + 3];
        float2 v0 = g2v[s0], v1 = g2v[s1], v2 = g2v[s2], v3 = g2v[s3];
        acc.x += (v0.x + v1.x) + (v2.x + v3.x);
        acc.y += (v0.y + v1.y) + (v2.y + v3.y);
    }
    for (; k < re; k++) {
        float2 v = g2v[d_col[k]];
        acc.x += v.x; acc.y += v.y;
    }
    const float di = d_dinv[i];
    *(float2*)(out + i * CC) =
        make_float2(fmaf(di, acc.x, b2[0]), fmaf(di, acc.y, b2[1]));
}

// ---------------- launch ----------------------------------------------------
extern "C" void kernel_launch(void* const* d_in, const int* in_sizes, int n_in,
                              void* d_out, int out_size) {
    const float* x  = (const float*)d_in[0];
    const void*  ei = d_in[1];
    const float* W1 = (const float*)d_in[2];
    const float* b1 = (const float*)d_in[3];
    const float* W2 = (const float*)d_in[4];
    const float* b2 = (const float*)d_in[5];
    float* out = (float*)d_out;

    const int E = in_sizes[1] / 2;

    k_detect<<<1, 256>>>((const int*)ei);
    k_zero  <<<NB, 256>>>();
    k_count <<<(E + 255) / 256, 256>>>(ei, E);
    k_scan1 <<<NB, 256>>>();
    k_scan2 <<<1, 256>>>();
    k_scan3 <<<NB, 256>>>();
    k_bucket<<<(E + 255) / 256, 256>>>(ei, E);
    k_gemm1 <<<(NN + 127) / 128, 256>>>(x, W1);
    k_agg1  <<<(NN + 7) / 8, 256>>>(b1, W2);
    k_agg2  <<<(NN + 255) / 256, 256>>>(out, b2);
}